// round 6
// baseline (speedup 1.0000x reference)
#include <cuda_runtime.h>

#define N_NODES 100000
#define N_EDGES 1600000
#define D 64
#define SCAN_TILE 1024
#define SCAN_NBLK ((N_NODES + SCAN_TILE - 1) / SCAN_TILE)   // 98

// ---------------- scratch (no allocs allowed) ----------------
__device__ float g_h[(size_t)N_NODES * D];       // layer-1 output
__device__ float g_projL[(size_t)N_NODES * D];   // feat @ Wl^T
__device__ float g_projR[(size_t)N_NODES * D];   // feat @ Wr^T
__device__ int   g_deg[N_NODES];
__device__ int   g_off[N_NODES];
__device__ int   g_pos[N_NODES];
__device__ int   g_csr[N_EDGES];
__device__ unsigned long long g_status[SCAN_NBLK];  // lookback: flag<<32 | sum

// ---------------- inline dtype detection (per-warp) ----------------
__device__ __forceinline__ int warp_is64(const unsigned* __restrict__ w) {
    unsigned v = w[2 * (threadIdx.x & 31) + 1];
    return __ballot_sync(0xffffffffu, v != 0) == 0;
}
__device__ __forceinline__ int edge_at(const void* ei, long long pos, int is64) {
    return is64 ? (int)((const long long*)ei)[pos]
                : ((const int*)ei)[pos];
}

// ---------------- CSR build ----------------
__global__ __launch_bounds__(256) void hist_kernel(const void* __restrict__ ei) {
    int is64 = warp_is64((const unsigned*)ei);
    int e = blockIdx.x * 256 + threadIdx.x;
    if (e >= N_EDGES) return;
    int dst = edge_at(ei, (long long)N_EDGES + e, is64);
    atomicAdd(&g_deg[dst], 1);
}

// single-pass exclusive scan with decoupled lookback (98 blocks, co-resident)
__global__ __launch_bounds__(256) void scan_lookback_kernel() {
    const unsigned FULL = 0xffffffffu;
    int b = blockIdx.x;
    int base = b * SCAN_TILE;
    int idx0 = base + threadIdx.x * 4;
    int v[4];
#pragma unroll
    for (int j = 0; j < 4; j++)
        v[j] = (idx0 + j < N_NODES) ? g_deg[idx0 + j] : 0;
    int tsum = v[0] + v[1] + v[2] + v[3];

    int lane = threadIdx.x & 31, wid = threadIdx.x >> 5;
    int s = tsum;
#pragma unroll
    for (int o = 1; o < 32; o <<= 1) {
        int t = __shfl_up_sync(FULL, s, o);
        if (lane >= o) s += t;
    }
    __shared__ int wsum[8];
    __shared__ int sprefix;
    if (lane == 31) wsum[wid] = s;
    __syncthreads();
    if (wid == 0) {
        int ws = (lane < 8) ? wsum[lane] : 0;
#pragma unroll
        for (int o = 1; o < 8; o <<= 1) {
            int t = __shfl_up_sync(FULL, ws, o);
            if (lane >= o) ws += t;
        }
        if (lane < 8) wsum[lane] = ws;
    }
    __syncthreads();
    int excl = s - tsum + (wid > 0 ? wsum[wid - 1] : 0);
    int total = wsum[7];

    if (wid == 7) {
        if (lane == 31) {
            unsigned long long pk =
                ((unsigned long long)(b == 0 ? 2u : 1u) << 32) | (unsigned)total;
            atomicExch(&g_status[b], pk);
        }
        int prefix = 0;
        if (b > 0) {
            int w = 0;
            bool done = false;
            while (!done) {
                int idx = b - 32 * (w + 1) + lane;
                int flag, val;
                do {
                    if (idx >= 0) {
                        unsigned long long st = atomicAdd(&g_status[idx], 0ULL);
                        flag = (int)(st >> 32);
                        val = (int)(st & 0xffffffffu);
                    } else { flag = 2; val = 0; }
                } while (__ballot_sync(FULL, flag == 0));
                unsigned m2 = __ballot_sync(FULL, flag == 2);
                int contrib;
                if (m2) {
                    int h = 31 - __clz(m2);
                    contrib = (lane >= h) ? val : 0;
                    done = true;
                } else {
                    contrib = val;
                    w++;
                }
#pragma unroll
                for (int o = 16; o; o >>= 1)
                    contrib += __shfl_down_sync(FULL, contrib, o);
                prefix += __shfl_sync(FULL, contrib, 0);
            }
            if (lane == 31)
                atomicExch(&g_status[b],
                           (2ULL << 32) | (unsigned)(prefix + total));
        }
        if (lane == 0) sprefix = prefix;
    }
    __syncthreads();

    int run = excl + sprefix;
#pragma unroll
    for (int j = 0; j < 4; j++) {
        if (idx0 + j < N_NODES) { g_off[idx0 + j] = run; g_pos[idx0 + j] = run; }
        run += v[j];
    }
}

__global__ __launch_bounds__(256) void scatter_kernel(const void* __restrict__ ei) {
    int is64 = warp_is64((const unsigned*)ei);
    int e = blockIdx.x * 256 + threadIdx.x;
    if (e >= N_EDGES) return;
    int src = edge_at(ei, e, is64);
    int dst = edge_at(ei, (long long)N_EDGES + e, is64);
    int p = atomicAdd(&g_pos[dst], 1);
    g_csr[p] = src;
}

// ---------------- projection GEMM: [projL|projR] = feat @ [Wl|Wr]^T ----------------
// Tile 128 nodes x 128 cols, 256 threads, 8x8 per thread. k-major smem,
// pad 132 -> conflict-free STS (warps span n/c), aligned float4 LDS.
#define XPAD 132
#define GEMM_SMEM (2 * 64 * XPAD * 4)

__global__ __launch_bounds__(256) void proj_kernel(const float* __restrict__ feat_param,
                                                   const float* __restrict__ Wl,
                                                   const float* __restrict__ Wr) {
    extern __shared__ float sm[];
    float (*Xs)[XPAD] = (float(*)[XPAD])sm;              // [k][node]
    float (*Ws)[XPAD] = (float(*)[XPAD])(sm + 64 * XPAD); // [k][col 0..127]

    const float* feat = feat_param ? feat_param : g_h;
    int tid = threadIdx.x;
    int nb = blockIdx.x * 128;

    // Ws: 2 x 64x64 floats = 2048 float4 items, transposed to k-major
#pragma unroll
    for (int it = 0; it < 8; it++) {
        int item = it * 256 + tid;
        int c = item & 127, kc = item >> 7;          // kc 0..15
        const float* Wsrc = (c < 64) ? (Wl + c * 64) : (Wr + (size_t)(c - 64) * 64);
        float4 w = *(const float4*)(Wsrc + kc * 4);
        Ws[kc * 4 + 0][c] = w.x;
        Ws[kc * 4 + 1][c] = w.y;
        Ws[kc * 4 + 2][c] = w.z;
        Ws[kc * 4 + 3][c] = w.w;
    }
    // Xs: 128 nodes x 16 chunks
#pragma unroll
    for (int it = 0; it < 8; it++) {
        int item = it * 256 + tid;
        int n = item & 127, kc = item >> 7;
        int node = nb + n;
        float4 v = make_float4(0.f, 0.f, 0.f, 0.f);
        if (node < N_NODES)
            v = *(const float4*)(feat + (size_t)node * D + kc * 4);
        Xs[kc * 4 + 0][n] = v.x;
        Xs[kc * 4 + 1][n] = v.y;
        Xs[kc * 4 + 2][n] = v.z;
        Xs[kc * 4 + 3][n] = v.w;
    }
    __syncthreads();

    int tc = tid & 15;      // 8 cols each
    int tn = tid >> 4;      // 8 nodes each
    float acc[8][8];
#pragma unroll
    for (int i = 0; i < 8; i++)
#pragma unroll
        for (int j = 0; j < 8; j++) acc[i][j] = 0.f;

#pragma unroll 4
    for (int k = 0; k < 64; k++) {
        float4 xa = *(const float4*)&Xs[k][tn * 8];
        float4 xb = *(const float4*)&Xs[k][tn * 8 + 4];
        float4 wa = *(const float4*)&Ws[k][tc * 8];
        float4 wb = *(const float4*)&Ws[k][tc * 8 + 4];
        float xv[8] = {xa.x, xa.y, xa.z, xa.w, xb.x, xb.y, xb.z, xb.w};
        float wv[8] = {wa.x, wa.y, wa.z, wa.w, wb.x, wb.y, wb.z, wb.w};
#pragma unroll
        for (int i = 0; i < 8; i++)
#pragma unroll
            for (int j = 0; j < 8; j++)
                acc[i][j] += xv[i] * wv[j];
    }

    // epilogue: tc<8 -> projL cols tc*8.. ; tc>=8 -> projR cols (tc-8)*8..
    float* dst = (tc < 8) ? g_projL : g_projR;
    int cbase = (tc & 7) * 8;
#pragma unroll
    for (int i = 0; i < 8; i++) {
        int node = nb + tn * 8 + i;
        if (node < N_NODES) {
            *(float4*)(dst + (size_t)node * D + cbase) =
                make_float4(acc[i][0], acc[i][1], acc[i][2], acc[i][3]);
            *(float4*)(dst + (size_t)node * D + cbase + 4) =
                make_float4(acc[i][4], acc[i][5], acc[i][6], acc[i][7]);
        }
    }
}

// ---------------- combine: out_i = mean_j projL_j + projR_i + b (+relu) ----------------
__global__ __launch_bounds__(256) void agg_combine_kernel(const float* __restrict__ b,
                                                          float* __restrict__ out_param,
                                                          int do_relu) {
    int t = blockIdx.x * 256 + threadIdx.x;
    int node = t >> 4;
    int c = t & 15;
    if (node >= N_NODES) return;
    float* out = out_param ? out_param : g_h;

    const int beg = g_off[node];
    const int n = g_deg[node];
    const float* fp = g_projL + c * 4;
    float4 acc = make_float4(0.f, 0.f, 0.f, 0.f);
    int j = 0;
    for (; j + 4 <= n; j += 4) {
        int s0 = g_csr[beg + j + 0];
        int s1 = g_csr[beg + j + 1];
        int s2 = g_csr[beg + j + 2];
        int s3 = g_csr[beg + j + 3];
        float4 v0 = *(const float4*)(fp + (size_t)s0 * D);
        float4 v1 = *(const float4*)(fp + (size_t)s1 * D);
        float4 v2 = *(const float4*)(fp + (size_t)s2 * D);
        float4 v3 = *(const float4*)(fp + (size_t)s3 * D);
        acc.x += v0.x + v1.x + v2.x + v3.x;
        acc.y += v0.y + v1.y + v2.y + v3.y;
        acc.z += v0.z + v1.z + v2.z + v3.z;
        acc.w += v0.w + v1.w + v2.w + v3.w;
    }
    for (; j < n; j++) {
        int sidx = g_csr[beg + j];
        float4 v = *(const float4*)(fp + (size_t)sidx * D);
        acc.x += v.x; acc.y += v.y; acc.z += v.z; acc.w += v.w;
    }
    float inv = 1.0f / fmaxf((float)n, 1.0f);
    float4 xr = *(const float4*)(g_projR + (size_t)node * D + c * 4);
    float4 bv = *(const float4*)(b + c * 4);
    float4 o;
    o.x = acc.x * inv + xr.x + bv.x;
    o.y = acc.y * inv + xr.y + bv.y;
    o.z = acc.z * inv + xr.z + bv.z;
    o.w = acc.w * inv + xr.w + bv.w;
    if (do_relu) {
        o.x = fmaxf(o.x, 0.f); o.y = fmaxf(o.y, 0.f);
        o.z = fmaxf(o.z, 0.f); o.w = fmaxf(o.w, 0.f);
    }
    *(float4*)(out + (size_t)node * D + c * 4) = o;
}

// ---------------- launch (fork CSR build onto a side stream) ----------------
extern "C" void kernel_launch(void* const* d_in, const int* in_sizes, int n_in,
                              void* d_out, int out_size) {
    const float* x   = (const float*)d_in[0];
    const void*  ei  = d_in[1];
    const float* W1l = (const float*)d_in[2];
    const float* W1r = (const float*)d_in[3];
    const float* b1  = (const float*)d_in[4];
    const float* W2l = (const float*)d_in[5];
    const float* W2r = (const float*)d_in[6];
    const float* b2  = (const float*)d_in[7];
    float* out = (float*)d_out;

    static cudaStream_t s_side = nullptr;
    static cudaEvent_t ev_fork = nullptr, ev_join = nullptr;
    static bool attr_set = false;
    if (!s_side) {
        // created on the (uncaptured) correctness call; reused during capture
        cudaStreamCreateWithFlags(&s_side, cudaStreamNonBlocking);
        cudaEventCreateWithFlags(&ev_fork, cudaEventDisableTiming);
        cudaEventCreateWithFlags(&ev_join, cudaEventDisableTiming);
    }
    if (!attr_set) {
        cudaFuncSetAttribute(proj_kernel,
                             cudaFuncAttributeMaxDynamicSharedMemorySize, GEMM_SMEM);
        attr_set = true;
    }

    const int E_BLOCKS   = (N_EDGES + 255) / 256;
    const int MM_BLOCKS  = (N_NODES + 127) / 128;
    const int AGG_BLOCKS = (N_NODES * 16 + 255) / 256;

    void* p_deg = nullptr;
    void* p_st  = nullptr;
    cudaGetSymbolAddress(&p_deg, g_deg);
    cudaGetSymbolAddress(&p_st, g_status);

    // fork: CSR build runs on side stream, concurrent with layer-1 GEMM
    cudaEventRecord(ev_fork, 0);
    cudaStreamWaitEvent(s_side, ev_fork, 0);
    cudaMemsetAsync(p_deg, 0, N_NODES * sizeof(int), s_side);
    cudaMemsetAsync(p_st, 0, SCAN_NBLK * sizeof(unsigned long long), s_side);
    hist_kernel<<<E_BLOCKS, 256, 0, s_side>>>(ei);
    scan_lookback_kernel<<<SCAN_NBLK, 256, 0, s_side>>>();
    scatter_kernel<<<E_BLOCKS, 256, 0, s_side>>>(ei);
    cudaEventRecord(ev_join, s_side);

    // layer-1 projection (independent of CSR)
    proj_kernel<<<MM_BLOCKS, 256, GEMM_SMEM>>>(x, W1l, W1r);

    // join, then the serial chain
    cudaStreamWaitEvent(0, ev_join, 0);
    agg_combine_kernel<<<AGG_BLOCKS, 256>>>(b1, nullptr, 1);       // -> g_h (relu)
    proj_kernel<<<MM_BLOCKS, 256, GEMM_SMEM>>>(nullptr, W2l, W2r); // g_h proj
    agg_combine_kernel<<<AGG_BLOCKS, 256>>>(b2, out, 0);           // -> d_out
}

// round 7
// speedup vs baseline: 1.1422x; 1.1422x over previous
#include <cuda_runtime.h>
#include <cuda_fp16.h>

#define N_NODES 100000
#define N_EDGES 1600000
#define D 64
#define SCAN_TILE 1024
#define SCAN_NBLK ((N_NODES + SCAN_TILE - 1) / SCAN_TILE)   // 98

// ---------------- scratch (no allocs allowed) ----------------
__device__ float  g_h[(size_t)N_NODES * D];        // layer-1 output
__device__ __half g_projL16[(size_t)N_NODES * D];  // feat @ Wl^T (fp16, gathered per-edge)
__device__ float  g_projR[(size_t)N_NODES * D];    // feat @ Wr^T (fp32)
__device__ int    g_deg[N_NODES];
__device__ int    g_off[N_NODES];
__device__ int    g_pos[N_NODES];
__device__ int    g_csr[N_EDGES];
__device__ unsigned long long g_status[SCAN_NBLK];  // lookback: flag<<32 | sum

// ---------------- inline dtype detection (per-warp) ----------------
__device__ __forceinline__ int warp_is64(const unsigned* __restrict__ w) {
    unsigned v = w[2 * (threadIdx.x & 31) + 1];
    return __ballot_sync(0xffffffffu, v != 0) == 0;
}
__device__ __forceinline__ int edge_at(const void* ei, long long pos, int is64) {
    return is64 ? (int)((const long long*)ei)[pos]
                : ((const int*)ei)[pos];
}

// ---------------- CSR build ----------------
__global__ __launch_bounds__(256) void hist_kernel(const void* __restrict__ ei) {
    int is64 = warp_is64((const unsigned*)ei);
    int e = blockIdx.x * 256 + threadIdx.x;
    if (e >= N_EDGES) return;
    int dst = edge_at(ei, (long long)N_EDGES + e, is64);
    atomicAdd(&g_deg[dst], 1);
}

// single-pass exclusive scan with decoupled lookback (98 blocks, co-resident)
__global__ __launch_bounds__(256) void scan_lookback_kernel() {
    const unsigned FULL = 0xffffffffu;
    int b = blockIdx.x;
    int base = b * SCAN_TILE;
    int idx0 = base + threadIdx.x * 4;
    int v[4];
#pragma unroll
    for (int j = 0; j < 4; j++)
        v[j] = (idx0 + j < N_NODES) ? g_deg[idx0 + j] : 0;
    int tsum = v[0] + v[1] + v[2] + v[3];

    int lane = threadIdx.x & 31, wid = threadIdx.x >> 5;
    int s = tsum;
#pragma unroll
    for (int o = 1; o < 32; o <<= 1) {
        int t = __shfl_up_sync(FULL, s, o);
        if (lane >= o) s += t;
    }
    __shared__ int wsum[8];
    __shared__ int sprefix;
    if (lane == 31) wsum[wid] = s;
    __syncthreads();
    if (wid == 0) {
        int ws = (lane < 8) ? wsum[lane] : 0;
#pragma unroll
        for (int o = 1; o < 8; o <<= 1) {
            int t = __shfl_up_sync(FULL, ws, o);
            if (lane >= o) ws += t;
        }
        if (lane < 8) wsum[lane] = ws;
    }
    __syncthreads();
    int excl = s - tsum + (wid > 0 ? wsum[wid - 1] : 0);
    int total = wsum[7];

    if (wid == 7) {
        if (lane == 31) {
            unsigned long long pk =
                ((unsigned long long)(b == 0 ? 2u : 1u) << 32) | (unsigned)total;
            atomicExch(&g_status[b], pk);
        }
        int prefix = 0;
        if (b > 0) {
            int w = 0;
            bool done = false;
            while (!done) {
                int idx = b - 32 * (w + 1) + lane;
                int flag, val;
                do {
                    if (idx >= 0) {
                        unsigned long long st = atomicAdd(&g_status[idx], 0ULL);
                        flag = (int)(st >> 32);
                        val = (int)(st & 0xffffffffu);
                    } else { flag = 2; val = 0; }
                } while (__ballot_sync(FULL, flag == 0));
                unsigned m2 = __ballot_sync(FULL, flag == 2);
                int contrib;
                if (m2) {
                    int h = 31 - __clz(m2);
                    contrib = (lane >= h) ? val : 0;
                    done = true;
                } else {
                    contrib = val;
                    w++;
                }
#pragma unroll
                for (int o = 16; o; o >>= 1)
                    contrib += __shfl_down_sync(FULL, contrib, o);
                prefix += __shfl_sync(FULL, contrib, 0);
            }
            if (lane == 31)
                atomicExch(&g_status[b],
                           (2ULL << 32) | (unsigned)(prefix + total));
        }
        if (lane == 0) sprefix = prefix;
    }
    __syncthreads();

    int run = excl + sprefix;
#pragma unroll
    for (int j = 0; j < 4; j++) {
        if (idx0 + j < N_NODES) { g_off[idx0 + j] = run; g_pos[idx0 + j] = run; }
        run += v[j];
    }
}

__global__ __launch_bounds__(256) void scatter_kernel(const void* __restrict__ ei) {
    int is64 = warp_is64((const unsigned*)ei);
    int e = blockIdx.x * 256 + threadIdx.x;
    if (e >= N_EDGES) return;
    int src = edge_at(ei, e, is64);
    int dst = edge_at(ei, (long long)N_EDGES + e, is64);
    int p = atomicAdd(&g_pos[dst], 1);
    g_csr[p] = src;
}

// ---------------- projection GEMM: projL(fp16) | projR(fp32) = feat @ [Wl|Wr]^T ----------------
#define XPAD 132
#define GEMM_SMEM (2 * 64 * XPAD * 4)

__global__ __launch_bounds__(256) void proj_kernel(const float* __restrict__ feat_param,
                                                   const float* __restrict__ Wl,
                                                   const float* __restrict__ Wr) {
    extern __shared__ float sm[];
    float (*Xs)[XPAD] = (float(*)[XPAD])sm;               // [k][node]
    float (*Ws)[XPAD] = (float(*)[XPAD])(sm + 64 * XPAD); // [k][col 0..127]

    const float* feat = feat_param ? feat_param : g_h;
    int tid = threadIdx.x;
    int nb = blockIdx.x * 128;

#pragma unroll
    for (int it = 0; it < 8; it++) {
        int item = it * 256 + tid;
        int c = item & 127, kc = item >> 7;          // kc 0..15
        const float* Wsrc = (c < 64) ? (Wl + c * 64) : (Wr + (size_t)(c - 64) * 64);
        float4 w = *(const float4*)(Wsrc + kc * 4);
        Ws[kc * 4 + 0][c] = w.x;
        Ws[kc * 4 + 1][c] = w.y;
        Ws[kc * 4 + 2][c] = w.z;
        Ws[kc * 4 + 3][c] = w.w;
    }
#pragma unroll
    for (int it = 0; it < 8; it++) {
        int item = it * 256 + tid;
        int n = item & 127, kc = item >> 7;
        int node = nb + n;
        float4 v = make_float4(0.f, 0.f, 0.f, 0.f);
        if (node < N_NODES)
            v = *(const float4*)(feat + (size_t)node * D + kc * 4);
        Xs[kc * 4 + 0][n] = v.x;
        Xs[kc * 4 + 1][n] = v.y;
        Xs[kc * 4 + 2][n] = v.z;
        Xs[kc * 4 + 3][n] = v.w;
    }
    __syncthreads();

    int tc = tid & 15;      // 8 cols each
    int tn = tid >> 4;      // 8 nodes each
    float acc[8][8];
#pragma unroll
    for (int i = 0; i < 8; i++)
#pragma unroll
        for (int j = 0; j < 8; j++) acc[i][j] = 0.f;

#pragma unroll 4
    for (int k = 0; k < 64; k++) {
        float4 xa = *(const float4*)&Xs[k][tn * 8];
        float4 xb = *(const float4*)&Xs[k][tn * 8 + 4];
        float4 wa = *(const float4*)&Ws[k][tc * 8];
        float4 wb = *(const float4*)&Ws[k][tc * 8 + 4];
        float xv[8] = {xa.x, xa.y, xa.z, xa.w, xb.x, xb.y, xb.z, xb.w};
        float wv[8] = {wa.x, wa.y, wa.z, wa.w, wb.x, wb.y, wb.z, wb.w};
#pragma unroll
        for (int i = 0; i < 8; i++)
#pragma unroll
            for (int j = 0; j < 8; j++)
                acc[i][j] += xv[i] * wv[j];
    }

    // epilogue: tc<8 -> projL (fp16); tc>=8 -> projR (fp32)
    int cbase = (tc & 7) * 8;
    if (tc < 8) {
#pragma unroll
        for (int i = 0; i < 8; i++) {
            int node = nb + tn * 8 + i;
            if (node < N_NODES) {
                __half2 h[4];
                h[0] = __floats2half2_rn(acc[i][0], acc[i][1]);
                h[1] = __floats2half2_rn(acc[i][2], acc[i][3]);
                h[2] = __floats2half2_rn(acc[i][4], acc[i][5]);
                h[3] = __floats2half2_rn(acc[i][6], acc[i][7]);
                *(float4*)(g_projL16 + (size_t)node * D + cbase) = *(float4*)h;
            }
        }
    } else {
#pragma unroll
        for (int i = 0; i < 8; i++) {
            int node = nb + tn * 8 + i;
            if (node < N_NODES) {
                *(float4*)(g_projR + (size_t)node * D + cbase) =
                    make_float4(acc[i][0], acc[i][1], acc[i][2], acc[i][3]);
                *(float4*)(g_projR + (size_t)node * D + cbase + 4) =
                    make_float4(acc[i][4], acc[i][5], acc[i][6], acc[i][7]);
            }
        }
    }
}

// ---------------- combine: out_i = mean_j projL_j + projR_i + b (+relu) ----------------
// 8 threads/node; each owns 8 consecutive cols = one 16B fp16 load per neighbor.
__device__ __forceinline__ void acc_h8(float a[8], float4 raw) {
    __half2* hp = (__half2*)&raw;
    float2 f0 = __half22float2(hp[0]);
    float2 f1 = __half22float2(hp[1]);
    float2 f2 = __half22float2(hp[2]);
    float2 f3 = __half22float2(hp[3]);
    a[0] += f0.x; a[1] += f0.y; a[2] += f1.x; a[3] += f1.y;
    a[4] += f2.x; a[5] += f2.y; a[6] += f3.x; a[7] += f3.y;
}

__global__ __launch_bounds__(256) void agg_combine_kernel(const float* __restrict__ b,
                                                          float* __restrict__ out_param,
                                                          int do_relu) {
    int t = blockIdx.x * 256 + threadIdx.x;
    int node = t >> 3;
    int c = t & 7;               // 8 cols each
    if (node >= N_NODES) return;
    float* out = out_param ? out_param : g_h;

    const int beg = g_off[node];
    const int n = g_deg[node];
    const __half* fp = g_projL16 + c * 8;
    float a[8] = {0.f, 0.f, 0.f, 0.f, 0.f, 0.f, 0.f, 0.f};
    int j = 0;
    for (; j + 4 <= n; j += 4) {
        int s0 = g_csr[beg + j + 0];
        int s1 = g_csr[beg + j + 1];
        int s2 = g_csr[beg + j + 2];
        int s3 = g_csr[beg + j + 3];
        float4 r0 = *(const float4*)(fp + (size_t)s0 * D);
        float4 r1 = *(const float4*)(fp + (size_t)s1 * D);
        float4 r2 = *(const float4*)(fp + (size_t)s2 * D);
        float4 r3 = *(const float4*)(fp + (size_t)s3 * D);
        acc_h8(a, r0); acc_h8(a, r1); acc_h8(a, r2); acc_h8(a, r3);
    }
    for (; j < n; j++) {
        int sidx = g_csr[beg + j];
        acc_h8(a, *(const float4*)(fp + (size_t)sidx * D));
    }
    float inv = 1.0f / fmaxf((float)n, 1.0f);
    float4 xr0 = *(const float4*)(g_projR + (size_t)node * D + c * 8);
    float4 xr1 = *(const float4*)(g_projR + (size_t)node * D + c * 8 + 4);
    float4 bv0 = *(const float4*)(b + c * 8);
    float4 bv1 = *(const float4*)(b + c * 8 + 4);
    float4 o0, o1;
    o0.x = a[0] * inv + xr0.x + bv0.x;
    o0.y = a[1] * inv + xr0.y + bv0.y;
    o0.z = a[2] * inv + xr0.z + bv0.z;
    o0.w = a[3] * inv + xr0.w + bv0.w;
    o1.x = a[4] * inv + xr1.x + bv1.x;
    o1.y = a[5] * inv + xr1.y + bv1.y;
    o1.z = a[6] * inv + xr1.z + bv1.z;
    o1.w = a[7] * inv + xr1.w + bv1.w;
    if (do_relu) {
        o0.x = fmaxf(o0.x, 0.f); o0.y = fmaxf(o0.y, 0.f);
        o0.z = fmaxf(o0.z, 0.f); o0.w = fmaxf(o0.w, 0.f);
        o1.x = fmaxf(o1.x, 0.f); o1.y = fmaxf(o1.y, 0.f);
        o1.z = fmaxf(o1.z, 0.f); o1.w = fmaxf(o1.w, 0.f);
    }
    *(float4*)(out + (size_t)node * D + c * 8) = o0;
    *(float4*)(out + (size_t)node * D + c * 8 + 4) = o1;
}

// ---------------- launch (fork CSR build onto a side stream) ----------------
extern "C" void kernel_launch(void* const* d_in, const int* in_sizes, int n_in,
                              void* d_out, int out_size) {
    const float* x   = (const float*)d_in[0];
    const void*  ei  = d_in[1];
    const float* W1l = (const float*)d_in[2];
    const float* W1r = (const float*)d_in[3];
    const float* b1  = (const float*)d_in[4];
    const float* W2l = (const float*)d_in[5];
    const float* W2r = (const float*)d_in[6];
    const float* b2  = (const float*)d_in[7];
    float* out = (float*)d_out;

    static cudaStream_t s_side = nullptr;
    static cudaEvent_t ev_fork = nullptr, ev_join = nullptr;
    static bool attr_set = false;
    if (!s_side) {
        cudaStreamCreateWithFlags(&s_side, cudaStreamNonBlocking);
        cudaEventCreateWithFlags(&ev_fork, cudaEventDisableTiming);
        cudaEventCreateWithFlags(&ev_join, cudaEventDisableTiming);
    }
    if (!attr_set) {
        cudaFuncSetAttribute(proj_kernel,
                             cudaFuncAttributeMaxDynamicSharedMemorySize, GEMM_SMEM);
        attr_set = true;
    }

    const int E_BLOCKS   = (N_EDGES + 255) / 256;
    const int MM_BLOCKS  = (N_NODES + 127) / 128;
    const int AGG_BLOCKS = (N_NODES * 8 + 255) / 256;

    void* p_deg = nullptr;
    void* p_st  = nullptr;
    cudaGetSymbolAddress(&p_deg, g_deg);
    cudaGetSymbolAddress(&p_st, g_status);

    // fork: CSR build runs on side stream, concurrent with layer-1 GEMM
    cudaEventRecord(ev_fork, 0);
    cudaStreamWaitEvent(s_side, ev_fork, 0);
    cudaMemsetAsync(p_deg, 0, N_NODES * sizeof(int), s_side);
    cudaMemsetAsync(p_st, 0, SCAN_NBLK * sizeof(unsigned long long), s_side);
    hist_kernel<<<E_BLOCKS, 256, 0, s_side>>>(ei);
    scan_lookback_kernel<<<SCAN_NBLK, 256, 0, s_side>>>();
    scatter_kernel<<<E_BLOCKS, 256, 0, s_side>>>(ei);
    cudaEventRecord(ev_join, s_side);

    // layer-1 projection (independent of CSR)
    proj_kernel<<<MM_BLOCKS, 256, GEMM_SMEM>>>(x, W1l, W1r);

    // join, then the serial chain
    cudaStreamWaitEvent(0, ev_join, 0);
    agg_combine_kernel<<<AGG_BLOCKS, 256>>>(b1, nullptr, 1);       // -> g_h (relu)
    proj_kernel<<<MM_BLOCKS, 256, GEMM_SMEM>>>(nullptr, W2l, W2r); // g_h proj
    agg_combine_kernel<<<AGG_BLOCKS, 256>>>(b2, out, 0);           // -> d_out
}

// round 8
// speedup vs baseline: 1.1510x; 1.0077x over previous
#include <cuda_runtime.h>
#include <cuda_fp16.h>

#define N_NODES 100000
#define N_EDGES 1600000
#define D 64
#define SCAN_TILE 1024
#define SCAN_NBLK ((N_NODES + SCAN_TILE - 1) / SCAN_TILE)   // 98

// ---------------- scratch (no allocs allowed) ----------------
__device__ float  g_h[(size_t)N_NODES * D];        // layer-1 output
__device__ __half g_projL16[(size_t)N_NODES * D];  // feat @ Wl^T (fp16, gathered per-edge)
__device__ float  g_projR[(size_t)N_NODES * D];    // feat @ Wr^T (fp32)
__device__ int    g_deg[N_NODES];
__device__ int    g_off[N_NODES];
__device__ int    g_pos[N_NODES];
__device__ int    g_csr[N_EDGES];
__device__ unsigned long long g_status[SCAN_NBLK];  // lookback: flag<<32 | sum

// ---------------- packed fp32x2 helpers (Blackwell) ----------------
__device__ __forceinline__ unsigned long long ffma2(unsigned long long a,
                                                    unsigned long long b,
                                                    unsigned long long c) {
    unsigned long long d;
    asm("fma.rn.f32x2 %0, %1, %2, %3;" : "=l"(d) : "l"(a), "l"(b), "l"(c));
    return d;
}
__device__ __forceinline__ unsigned long long dup2(float w) {
    unsigned long long d;
    asm("mov.b64 %0, {%1, %1};" : "=l"(d) : "f"(w));
    return d;
}
__device__ __forceinline__ float2 unpack2(unsigned long long v) {
    float2 f;
    asm("mov.b64 {%0, %1}, %2;" : "=f"(f.x), "=f"(f.y) : "l"(v));
    return f;
}

// ---------------- inline dtype detection (per-warp) ----------------
__device__ __forceinline__ int warp_is64(const unsigned* __restrict__ w) {
    unsigned v = w[2 * (threadIdx.x & 31) + 1];
    return __ballot_sync(0xffffffffu, v != 0) == 0;
}
__device__ __forceinline__ int edge_at(const void* ei, long long pos, int is64) {
    return is64 ? (int)((const long long*)ei)[pos]
                : ((const int*)ei)[pos];
}

// ---------------- CSR build ----------------
__global__ __launch_bounds__(256) void hist_kernel(const void* __restrict__ ei) {
    int is64 = warp_is64((const unsigned*)ei);
    int e = blockIdx.x * 256 + threadIdx.x;
    if (e >= N_EDGES) return;
    int dst = edge_at(ei, (long long)N_EDGES + e, is64);
    atomicAdd(&g_deg[dst], 1);
}

// single-pass exclusive scan with decoupled lookback (98 blocks, co-resident)
__global__ __launch_bounds__(256) void scan_lookback_kernel() {
    const unsigned FULL = 0xffffffffu;
    int b = blockIdx.x;
    int base = b * SCAN_TILE;
    int idx0 = base + threadIdx.x * 4;
    int v[4];
#pragma unroll
    for (int j = 0; j < 4; j++)
        v[j] = (idx0 + j < N_NODES) ? g_deg[idx0 + j] : 0;
    int tsum = v[0] + v[1] + v[2] + v[3];

    int lane = threadIdx.x & 31, wid = threadIdx.x >> 5;
    int s = tsum;
#pragma unroll
    for (int o = 1; o < 32; o <<= 1) {
        int t = __shfl_up_sync(FULL, s, o);
        if (lane >= o) s += t;
    }
    __shared__ int wsum[8];
    __shared__ int sprefix;
    if (lane == 31) wsum[wid] = s;
    __syncthreads();
    if (wid == 0) {
        int ws = (lane < 8) ? wsum[lane] : 0;
#pragma unroll
        for (int o = 1; o < 8; o <<= 1) {
            int t = __shfl_up_sync(FULL, ws, o);
            if (lane >= o) ws += t;
        }
        if (lane < 8) wsum[lane] = ws;
    }
    __syncthreads();
    int excl = s - tsum + (wid > 0 ? wsum[wid - 1] : 0);
    int total = wsum[7];

    if (wid == 7) {
        if (lane == 31) {
            unsigned long long pk =
                ((unsigned long long)(b == 0 ? 2u : 1u) << 32) | (unsigned)total;
            atomicExch(&g_status[b], pk);
        }
        int prefix = 0;
        if (b > 0) {
            int w = 0;
            bool done = false;
            while (!done) {
                int idx = b - 32 * (w + 1) + lane;
                int flag, val;
                do {
                    if (idx >= 0) {
                        unsigned long long st = atomicAdd(&g_status[idx], 0ULL);
                        flag = (int)(st >> 32);
                        val = (int)(st & 0xffffffffu);
                    } else { flag = 2; val = 0; }
                } while (__ballot_sync(FULL, flag == 0));
                unsigned m2 = __ballot_sync(FULL, flag == 2);
                int contrib;
                if (m2) {
                    int h = 31 - __clz(m2);
                    contrib = (lane >= h) ? val : 0;
                    done = true;
                } else {
                    contrib = val;
                    w++;
                }
#pragma unroll
                for (int o = 16; o; o >>= 1)
                    contrib += __shfl_down_sync(FULL, contrib, o);
                prefix += __shfl_sync(FULL, contrib, 0);
            }
            if (lane == 31)
                atomicExch(&g_status[b],
                           (2ULL << 32) | (unsigned)(prefix + total));
        }
        if (lane == 0) sprefix = prefix;
    }
    __syncthreads();

    int run = excl + sprefix;
#pragma unroll
    for (int j = 0; j < 4; j++) {
        if (idx0 + j < N_NODES) { g_off[idx0 + j] = run; g_pos[idx0 + j] = run; }
        run += v[j];
    }
}

__global__ __launch_bounds__(256) void scatter_kernel(const void* __restrict__ ei) {
    int is64 = warp_is64((const unsigned*)ei);
    int e = blockIdx.x * 256 + threadIdx.x;
    if (e >= N_EDGES) return;
    int src = edge_at(ei, e, is64);
    int dst = edge_at(ei, (long long)N_EDGES + e, is64);
    int p = atomicAdd(&g_pos[dst], 1);
    g_csr[p] = src;
}

// ---------------- projection GEMM: projL(fp16) | projR(fp32) = feat @ [Wl|Wr]^T ----------------
// 128 nodes x 128 cols per block, 256 threads, 8x8 per thread computed as
// 4 node-pairs x 8 cols in packed f32x2 (FFMA2): x pairs free via ulonglong2
// reinterpret of node-major Xs; w duplicated with mov.b64 (8/k, amortized x4).
#define XPAD 132
#define GEMM_SMEM (2 * 64 * XPAD * 4)

__global__ __launch_bounds__(256) void proj_kernel(const float* __restrict__ feat_param,
                                                   const float* __restrict__ Wl,
                                                   const float* __restrict__ Wr) {
    extern __shared__ float sm[];
    float (*Xs)[XPAD] = (float(*)[XPAD])sm;               // [k][node]
    float (*Ws)[XPAD] = (float(*)[XPAD])(sm + 64 * XPAD); // [k][col 0..127]

    const float* feat = feat_param ? feat_param : g_h;
    int tid = threadIdx.x;
    int nb = blockIdx.x * 128;

#pragma unroll
    for (int it = 0; it < 8; it++) {
        int item = it * 256 + tid;
        int c = item & 127, kc = item >> 7;          // kc 0..15
        const float* Wsrc = (c < 64) ? (Wl + c * 64) : (Wr + (size_t)(c - 64) * 64);
        float4 w = *(const float4*)(Wsrc + kc * 4);
        Ws[kc * 4 + 0][c] = w.x;
        Ws[kc * 4 + 1][c] = w.y;
        Ws[kc * 4 + 2][c] = w.z;
        Ws[kc * 4 + 3][c] = w.w;
    }
#pragma unroll
    for (int it = 0; it < 8; it++) {
        int item = it * 256 + tid;
        int n = item & 127, kc = item >> 7;
        int node = nb + n;
        float4 v = make_float4(0.f, 0.f, 0.f, 0.f);
        if (node < N_NODES)
            v = *(const float4*)(feat + (size_t)node * D + kc * 4);
        Xs[kc * 4 + 0][n] = v.x;
        Xs[kc * 4 + 1][n] = v.y;
        Xs[kc * 4 + 2][n] = v.z;
        Xs[kc * 4 + 3][n] = v.w;
    }
    __syncthreads();

    int tc = tid & 15;      // 8 cols each
    int tn = tid >> 4;      // 8 nodes each (4 pairs)
    unsigned long long acc2[4][8];
#pragma unroll
    for (int ip = 0; ip < 4; ip++)
#pragma unroll
        for (int j = 0; j < 8; j++) acc2[ip][j] = 0ULL;

#pragma unroll 4
    for (int k = 0; k < 64; k++) {
        // node pairs (even,odd) packed straight from smem — LDS.128, no packing
        ulonglong2 xa = *(const ulonglong2*)&Xs[k][tn * 8];
        ulonglong2 xb = *(const ulonglong2*)&Xs[k][tn * 8 + 4];
        unsigned long long xp[4] = {xa.x, xa.y, xb.x, xb.y};
        float4 wa = *(const float4*)&Ws[k][tc * 8];
        float4 wb = *(const float4*)&Ws[k][tc * 8 + 4];
        unsigned long long wp[8] = {dup2(wa.x), dup2(wa.y), dup2(wa.z), dup2(wa.w),
                                    dup2(wb.x), dup2(wb.y), dup2(wb.z), dup2(wb.w)};
#pragma unroll
        for (int ip = 0; ip < 4; ip++)
#pragma unroll
            for (int j = 0; j < 8; j++)
                acc2[ip][j] = ffma2(xp[ip], wp[j], acc2[ip][j]);
    }

    // epilogue: tc<8 -> projL (fp16); tc>=8 -> projR (fp32)
    int cbase = (tc & 7) * 8;
#pragma unroll
    for (int ip = 0; ip < 4; ip++) {
        float lo[8], hi[8];
#pragma unroll
        for (int j = 0; j < 8; j++) {
            float2 f = unpack2(acc2[ip][j]);
            lo[j] = f.x; hi[j] = f.y;
        }
        int node0 = nb + tn * 8 + ip * 2;
#pragma unroll
        for (int h = 0; h < 2; h++) {
            int node = node0 + h;
            const float* v = h ? hi : lo;
            if (node < N_NODES) {
                if (tc < 8) {
                    __half2 hp[4];
                    hp[0] = __floats2half2_rn(v[0], v[1]);
                    hp[1] = __floats2half2_rn(v[2], v[3]);
                    hp[2] = __floats2half2_rn(v[4], v[5]);
                    hp[3] = __floats2half2_rn(v[6], v[7]);
                    *(float4*)(g_projL16 + (size_t)node * D + cbase) = *(float4*)hp;
                } else {
                    *(float4*)(g_projR + (size_t)node * D + cbase) =
                        make_float4(v[0], v[1], v[2], v[3]);
                    *(float4*)(g_projR + (size_t)node * D + cbase + 4) =
                        make_float4(v[4], v[5], v[6], v[7]);
                }
            }
        }
    }
}

// ---------------- combine: out_i = mean_j projL_j + projR_i + b (+relu) ----------------
__device__ __forceinline__ void acc_h8(float a[8], float4 raw) {
    __half2* hp = (__half2*)&raw;
    float2 f0 = __half22float2(hp[0]);
    float2 f1 = __half22float2(hp[1]);
    float2 f2 = __half22float2(hp[2]);
    float2 f3 = __half22float2(hp[3]);
    a[0] += f0.x; a[1] += f0.y; a[2] += f1.x; a[3] += f1.y;
    a[4] += f2.x; a[5] += f2.y; a[6] += f3.x; a[7] += f3.y;
}

__global__ __launch_bounds__(256) void agg_combine_kernel(const float* __restrict__ b,
                                                          float* __restrict__ out_param,
                                                          int do_relu) {
    int t = blockIdx.x * 256 + threadIdx.x;
    int node = t >> 3;
    int c = t & 7;               // 8 cols each
    if (node >= N_NODES) return;
    float* out = out_param ? out_param : g_h;

    const int beg = g_off[node];
    const int n = g_deg[node];
    const __half* fp = g_projL16 + c * 8;
    float a[8] = {0.f, 0.f, 0.f, 0.f, 0.f, 0.f, 0.f, 0.f};
    int j = 0;
    for (; j + 4 <= n; j += 4) {
        int s0 = g_csr[beg + j + 0];
        int s1 = g_csr[beg + j + 1];
        int s2 = g_csr[beg + j + 2];
        int s3 = g_csr[beg + j + 3];
        float4 r0 = *(const float4*)(fp + (size_t)s0 * D);
        float4 r1 = *(const float4*)(fp + (size_t)s1 * D);
        float4 r2 = *(const float4*)(fp + (size_t)s2 * D);
        float4 r3 = *(const float4*)(fp + (size_t)s3 * D);
        acc_h8(a, r0); acc_h8(a, r1); acc_h8(a, r2); acc_h8(a, r3);
    }
    for (; j < n; j++) {
        int sidx = g_csr[beg + j];
        acc_h8(a, *(const float4*)(fp + (size_t)sidx * D));
    }
    float inv = 1.0f / fmaxf((float)n, 1.0f);
    float4 xr0 = *(const float4*)(g_projR + (size_t)node * D + c * 8);
    float4 xr1 = *(const float4*)(g_projR + (size_t)node * D + c * 8 + 4);
    float4 bv0 = *(const float4*)(b + c * 8);
    float4 bv1 = *(const float4*)(b + c * 8 + 4);
    float4 o0, o1;
    o0.x = a[0] * inv + xr0.x + bv0.x;
    o0.y = a[1] * inv + xr0.y + bv0.y;
    o0.z = a[2] * inv + xr0.z + bv0.z;
    o0.w = a[3] * inv + xr0.w + bv0.w;
    o1.x = a[4] * inv + xr1.x + bv1.x;
    o1.y = a[5] * inv + xr1.y + bv1.y;
    o1.z = a[6] * inv + xr1.z + bv1.z;
    o1.w = a[7] * inv + xr1.w + bv1.w;
    if (do_relu) {
        o0.x = fmaxf(o0.x, 0.f); o0.y = fmaxf(o0.y, 0.f);
        o0.z = fmaxf(o0.z, 0.f); o0.w = fmaxf(o0.w, 0.f);
        o1.x = fmaxf(o1.x, 0.f); o1.y = fmaxf(o1.y, 0.f);
        o1.z = fmaxf(o1.z, 0.f); o1.w = fmaxf(o1.w, 0.f);
    }
    *(float4*)(out + (size_t)node * D + c * 8) = o0;
    *(float4*)(out + (size_t)node * D + c * 8 + 4) = o1;
}

// ---------------- launch (fork CSR build onto a side stream) ----------------
extern "C" void kernel_launch(void* const* d_in, const int* in_sizes, int n_in,
                              void* d_out, int out_size) {
    const float* x   = (const float*)d_in[0];
    const void*  ei  = d_in[1];
    const float* W1l = (const float*)d_in[2];
    const float* W1r = (const float*)d_in[3];
    const float* b1  = (const float*)d_in[4];
    const float* W2l = (const float*)d_in[5];
    const float* W2r = (const float*)d_in[6];
    const float* b2  = (const float*)d_in[7];
    float* out = (float*)d_out;

    static cudaStream_t s_side = nullptr;
    static cudaEvent_t ev_fork = nullptr, ev_join = nullptr;
    static bool attr_set = false;
    if (!s_side) {
        cudaStreamCreateWithFlags(&s_side, cudaStreamNonBlocking);
        cudaEventCreateWithFlags(&ev_fork, cudaEventDisableTiming);
        cudaEventCreateWithFlags(&ev_join, cudaEventDisableTiming);
    }
    if (!attr_set) {
        cudaFuncSetAttribute(proj_kernel,
                             cudaFuncAttributeMaxDynamicSharedMemorySize, GEMM_SMEM);
        attr_set = true;
    }

    const int E_BLOCKS   = (N_EDGES + 255) / 256;
    const int MM_BLOCKS  = (N_NODES + 127) / 128;
    const int AGG_BLOCKS = (N_NODES * 8 + 255) / 256;

    void* p_deg = nullptr;
    void* p_st  = nullptr;
    cudaGetSymbolAddress(&p_deg, g_deg);
    cudaGetSymbolAddress(&p_st, g_status);

    // fork: CSR build runs on side stream, concurrent with layer-1 GEMM
    cudaEventRecord(ev_fork, 0);
    cudaStreamWaitEvent(s_side, ev_fork, 0);
    cudaMemsetAsync(p_deg, 0, N_NODES * sizeof(int), s_side);
    cudaMemsetAsync(p_st, 0, SCAN_NBLK * sizeof(unsigned long long), s_side);
    hist_kernel<<<E_BLOCKS, 256, 0, s_side>>>(ei);
    scan_lookback_kernel<<<SCAN_NBLK, 256, 0, s_side>>>();
    scatter_kernel<<<E_BLOCKS, 256, 0, s_side>>>(ei);
    cudaEventRecord(ev_join, s_side);

    // layer-1 projection (independent of CSR)
    proj_kernel<<<MM_BLOCKS, 256, GEMM_SMEM>>>(x, W1l, W1r);

    // join, then the serial chain
    cudaStreamWaitEvent(0, ev_join, 0);
    agg_combine_kernel<<<AGG_BLOCKS, 256>>>(b1, nullptr, 1);       // -> g_h (relu)
    proj_kernel<<<MM_BLOCKS, 256, GEMM_SMEM>>>(nullptr, W2l, W2r); // g_h proj
    agg_combine_kernel<<<AGG_BLOCKS, 256>>>(b2, out, 0);           // -> d_out
}

// round 10
// speedup vs baseline: 1.4604x; 1.2688x over previous
#include <cuda_runtime.h>
#include <cuda_fp16.h>
#include <cstdint>

#define N_NODES 100000
#define N_EDGES 1600000
#define D 64
#define SCAN_TILE 1024
#define SCAN_NBLK ((N_NODES + SCAN_TILE - 1) / SCAN_TILE)   // 98

// ---------------- scratch (no allocs allowed) ----------------
__device__ float  g_h[(size_t)N_NODES * D];        // layer-1 output
__device__ __half g_projL16[(size_t)N_NODES * D];  // feat @ Wl^T (fp16, gathered per-edge)
__device__ float  g_projR[(size_t)N_NODES * D];    // feat @ Wr^T (fp32)
__device__ int    g_deg[N_NODES];
__device__ int    g_off[N_NODES];
__device__ int    g_pos[N_NODES];
__device__ int    g_csr[N_EDGES];
__device__ unsigned long long g_status[SCAN_NBLK];  // lookback: flag<<32 | sum

// ---------------- mma.sync helpers (base PTX, works on sm_103 non-'a') ----------------
static __device__ __forceinline__ uint32_t smem_u32(const void* p) {
    uint32_t a;
    asm("{ .reg .u64 t; cvta.to.shared.u64 t, %1; cvt.u32.u64 %0, t; }"
        : "=r"(a) : "l"(p));
    return a;
}
static __device__ __forceinline__ void ldsm_x4(uint32_t* r, uint32_t addr) {
    asm volatile("ldmatrix.sync.aligned.m8n8.x4.shared.b16 {%0,%1,%2,%3}, [%4];"
                 : "=r"(r[0]), "=r"(r[1]), "=r"(r[2]), "=r"(r[3]) : "r"(addr));
}
static __device__ __forceinline__ void mma16816(float* c, const uint32_t* a,
                                                const uint32_t* b) {
    asm volatile(
        "mma.sync.aligned.m16n8k16.row.col.f32.f16.f16.f32 "
        "{%0,%1,%2,%3}, {%4,%5,%6,%7}, {%8,%9}, {%0,%1,%2,%3};"
        : "+f"(c[0]), "+f"(c[1]), "+f"(c[2]), "+f"(c[3])
        : "r"(a[0]), "r"(a[1]), "r"(a[2]), "r"(a[3]), "r"(b[0]), "r"(b[1]));
}

// ---------------- inline dtype detection (per-warp) ----------------
__device__ __forceinline__ int warp_is64(const unsigned* __restrict__ w) {
    unsigned v = w[2 * (threadIdx.x & 31) + 1];
    return __ballot_sync(0xffffffffu, v != 0) == 0;
}
__device__ __forceinline__ int edge_at(const void* ei, long long pos, int is64) {
    return is64 ? (int)((const long long*)ei)[pos]
                : ((const int*)ei)[pos];
}

// ---------------- CSR build ----------------
__global__ __launch_bounds__(256) void hist_kernel(const void* __restrict__ ei) {
    int is64 = warp_is64((const unsigned*)ei);
    int e = blockIdx.x * 256 + threadIdx.x;
    if (e >= N_EDGES) return;
    int dst = edge_at(ei, (long long)N_EDGES + e, is64);
    atomicAdd(&g_deg[dst], 1);
}

__global__ __launch_bounds__(256) void scan_lookback_kernel() {
    const unsigned FULL = 0xffffffffu;
    int b = blockIdx.x;
    int base = b * SCAN_TILE;
    int idx0 = base + threadIdx.x * 4;
    int v[4];
#pragma unroll
    for (int j = 0; j < 4; j++)
        v[j] = (idx0 + j < N_NODES) ? g_deg[idx0 + j] : 0;
    int tsum = v[0] + v[1] + v[2] + v[3];

    int lane = threadIdx.x & 31, wid = threadIdx.x >> 5;
    int s = tsum;
#pragma unroll
    for (int o = 1; o < 32; o <<= 1) {
        int t = __shfl_up_sync(FULL, s, o);
        if (lane >= o) s += t;
    }
    __shared__ int wsum[8];
    __shared__ int sprefix;
    if (lane == 31) wsum[wid] = s;
    __syncthreads();
    if (wid == 0) {
        int ws = (lane < 8) ? wsum[lane] : 0;
#pragma unroll
        for (int o = 1; o < 8; o <<= 1) {
            int t = __shfl_up_sync(FULL, ws, o);
            if (lane >= o) ws += t;
        }
        if (lane < 8) wsum[lane] = ws;
    }
    __syncthreads();
    int excl = s - tsum + (wid > 0 ? wsum[wid - 1] : 0);
    int total = wsum[7];

    if (wid == 7) {
        if (lane == 31) {
            unsigned long long pk =
                ((unsigned long long)(b == 0 ? 2u : 1u) << 32) | (unsigned)total;
            atomicExch(&g_status[b], pk);
        }
        int prefix = 0;
        if (b > 0) {
            int w = 0;
            bool done = false;
            while (!done) {
                int idx = b - 32 * (w + 1) + lane;
                int flag, val;
                do {
                    if (idx >= 0) {
                        unsigned long long st = atomicAdd(&g_status[idx], 0ULL);
                        flag = (int)(st >> 32);
                        val = (int)(st & 0xffffffffu);
                    } else { flag = 2; val = 0; }
                } while (__ballot_sync(FULL, flag == 0));
                unsigned m2 = __ballot_sync(FULL, flag == 2);
                int contrib;
                if (m2) {
                    int h = 31 - __clz(m2);
                    contrib = (lane >= h) ? val : 0;
                    done = true;
                } else {
                    contrib = val;
                    w++;
                }
#pragma unroll
                for (int o = 16; o; o >>= 1)
                    contrib += __shfl_down_sync(FULL, contrib, o);
                prefix += __shfl_sync(FULL, contrib, 0);
            }
            if (lane == 31)
                atomicExch(&g_status[b],
                           (2ULL << 32) | (unsigned)(prefix + total));
        }
        if (lane == 0) sprefix = prefix;
    }
    __syncthreads();

    int run = excl + sprefix;
#pragma unroll
    for (int j = 0; j < 4; j++) {
        if (idx0 + j < N_NODES) { g_off[idx0 + j] = run; g_pos[idx0 + j] = run; }
        run += v[j];
    }
}

__global__ __launch_bounds__(256) void scatter_kernel(const void* __restrict__ ei) {
    int is64 = warp_is64((const unsigned*)ei);
    int e = blockIdx.x * 256 + threadIdx.x;
    if (e >= N_EDGES) return;
    int src = edge_at(ei, e, is64);
    int dst = edge_at(ei, (long long)N_EDGES + e, is64);
    int p = atomicAdd(&g_pos[dst], 1);
    g_csr[p] = src;
}

// ---------------- tensor-core (HMMA) projection ----------------
// projL(fp16)|projR(fp32) = feat @ [Wl|Wr]^T per 128-node block.
// 256 threads = 8 warps in 4(M) x 2(N) grid; each warp 32 nodes x 64 cols.
// A[128x64] fp16 row-major smem, B=[Wl|Wr][128x64] fp16 (rows = output col,
// k-contig = col-major B fragment). ldmatrix.x4 + mma.m16n8k16 f32 accum.
#define SPAD 72   // half-stride per row (64 + 8 pad)

__global__ __launch_bounds__(256) void proj_mma_kernel(const float* __restrict__ feat_param,
                                                       const float* __restrict__ Wl,
                                                       const float* __restrict__ Wr) {
    __shared__ __half As[128][SPAD];
    __shared__ __half Bs[128][SPAD];

    const float* feat = feat_param ? feat_param : g_h;
    int tid = threadIdx.x;
    int nb = blockIdx.x * 128;

    // load + fp32->fp16 convert: thread -> (row, k-half)
    {
        int r = tid >> 1, h = tid & 1;
        // A: node features
        {
            int node = nb + r;
            __half2 tmp[16];
            if (node < N_NODES) {
                const float* src = feat + (size_t)node * D + h * 32;
#pragma unroll
                for (int q = 0; q < 8; q++) {
                    float4 f = *(const float4*)(src + q * 4);
                    tmp[2 * q + 0] = __floats2half2_rn(f.x, f.y);
                    tmp[2 * q + 1] = __floats2half2_rn(f.z, f.w);
                }
            } else {
#pragma unroll
                for (int q = 0; q < 16; q++) tmp[q] = __floats2half2_rn(0.f, 0.f);
            }
            float4* dst = (float4*)&As[r][h * 32];
#pragma unroll
            for (int q = 0; q < 4; q++) dst[q] = ((float4*)tmp)[q];
        }
        // B: weight rows (output col c): Wl rows 0-63, Wr rows 64-127
        {
            int c = r;
            const float* src = ((c < 64) ? (Wl + (size_t)c * 64)
                                         : (Wr + (size_t)(c - 64) * 64)) + h * 32;
            __half2 tmp[16];
#pragma unroll
            for (int q = 0; q < 8; q++) {
                float4 f = *(const float4*)(src + q * 4);
                tmp[2 * q + 0] = __floats2half2_rn(f.x, f.y);
                tmp[2 * q + 1] = __floats2half2_rn(f.z, f.w);
            }
            float4* dst = (float4*)&Bs[r][h * 32];
#pragma unroll
            for (int q = 0; q < 4; q++) dst[q] = ((float4*)tmp)[q];
        }
    }
    __syncthreads();

    int wid = tid >> 5, lane = tid & 31;
    int wm = wid & 3;       // M chunk (32 nodes)
    int wn = wid >> 2;      // N chunk (64 cols): 0 -> projL, 1 -> projR

    uint32_t a_base = smem_u32(&As[0][0]);
    uint32_t b_base = smem_u32(&Bs[0][0]);

    float acc[2][8][4];
#pragma unroll
    for (int i = 0; i < 2; i++)
#pragma unroll
        for (int t = 0; t < 8; t++)
#pragma unroll
            for (int q = 0; q < 4; q++) acc[i][t][q] = 0.f;

#pragma unroll
    for (int kc = 0; kc < 4; kc++) {
        // A fragments: two m16 tiles
        uint32_t af[2][4];
#pragma unroll
        for (int i = 0; i < 2; i++) {
            int row = wm * 32 + i * 16 + (lane & 15);
            int ko = kc * 16 + (lane >> 4) * 8;
            ldsm_x4(af[i], a_base + (uint32_t)(row * SPAD + ko) * 2);
        }
        // B fragments: four n16 groups, each ldmatrix.x4 = two n8 operand pairs
#pragma unroll
        for (int j = 0; j < 4; j++) {
            int m = lane >> 3;
            int n = wn * 64 + j * 16 + ((m & 2) ? 8 : 0) + (lane & 7);
            int ko = kc * 16 + ((m & 1) ? 8 : 0);
            uint32_t bf[4];
            ldsm_x4(bf, b_base + (uint32_t)(n * SPAD + ko) * 2);
#pragma unroll
            for (int i = 0; i < 2; i++) {
                mma16816(acc[i][j * 2 + 0], af[i], bf + 0);
                mma16816(acc[i][j * 2 + 1], af[i], bf + 2);
            }
        }
    }

    // epilogue: C frag (row = lane>>2 [+8], cols = (lane&3)*2 +0/1)
    int gr = lane >> 2, cp = (lane & 3) * 2;
#pragma unroll
    for (int i = 0; i < 2; i++) {
#pragma unroll
        for (int t = 0; t < 8; t++) {
            int col = wn * 64 + t * 8 + cp;   // 0-63 projL, 64-127 projR
#pragma unroll
            for (int hrow = 0; hrow < 2; hrow++) {
                int r = wm * 32 + i * 16 + gr + hrow * 8;
                int node = nb + r;
                if (node < N_NODES) {
                    float v0 = acc[i][t][hrow * 2 + 0];
                    float v1 = acc[i][t][hrow * 2 + 1];
                    if (wn == 0) {
                        *(__half2*)(g_projL16 + (size_t)node * D + col) =
                            __floats2half2_rn(v0, v1);
                    } else {
                        *(float2*)(g_projR + (size_t)node * D + (col - 64)) =
                            make_float2(v0, v1);
                    }
                }
            }
        }
    }
}

// ---------------- combine: out_i = mean_j projL_j + projR_i + b (+relu) ----------------
__device__ __forceinline__ void acc_h8(float a[8], float4 raw) {
    __half2* hp = (__half2*)&raw;
    float2 f0 = __half22float2(hp[0]);
    float2 f1 = __half22float2(hp[1]);
    float2 f2 = __half22float2(hp[2]);
    float2 f3 = __half22float2(hp[3]);
    a[0] += f0.x; a[1] += f0.y; a[2] += f1.x; a[3] += f1.y;
    a[4] += f2.x; a[5] += f2.y; a[6] += f3.x; a[7] += f3.y;
}

__global__ __launch_bounds__(256) void agg_combine_kernel(const float* __restrict__ b,
                                                          float* __restrict__ out_param,
                                                          int do_relu) {
    int t = blockIdx.x * 256 + threadIdx.x;
    int node = t >> 3;
    int c = t & 7;               // 8 cols each
    if (node >= N_NODES) return;
    float* out = out_param ? out_param : g_h;

    const int beg = g_off[node];
    const int n = g_deg[node];
    const __half* fp = g_projL16 + c * 8;
    float a[8] = {0.f, 0.f, 0.f, 0.f, 0.f, 0.f, 0.f, 0.f};
    int j = 0;
    for (; j + 4 <= n; j += 4) {
        int s0 = g_csr[beg + j + 0];
        int s1 = g_csr[beg + j + 1];
        int s2 = g_csr[beg + j + 2];
        int s3 = g_csr[beg + j + 3];
        float4 r0 = *(const float4*)(fp + (size_t)s0 * D);
        float4 r1 = *(const float4*)(fp + (size_t)s1 * D);
        float4 r2 = *(const float4*)(fp + (size_t)s2 * D);
        float4 r3 = *(const float4*)(fp + (size_t)s3 * D);
        acc_h8(a, r0); acc_h8(a, r1); acc_h8(a, r2); acc_h8(a, r3);
    }
    for (; j < n; j++) {
        int sidx = g_csr[beg + j];
        acc_h8(a, *(const float4*)(fp + (size_t)sidx * D));
    }
    float inv = 1.0f / fmaxf((float)n, 1.0f);
    float4 xr0 = *(const float4*)(g_projR + (size_t)node * D + c * 8);
    float4 xr1 = *(const float4*)(g_projR + (size_t)node * D + c * 8 + 4);
    float4 bv0 = *(const float4*)(b + c * 8);
    float4 bv1 = *(const float4*)(b + c * 8 + 4);
    float4 o0, o1;
    o0.x = a[0] * inv + xr0.x + bv0.x;
    o0.y = a[1] * inv + xr0.y + bv0.y;
    o0.z = a[2] * inv + xr0.z + bv0.z;
    o0.w = a[3] * inv + xr0.w + bv0.w;
    o1.x = a[4] * inv + xr1.x + bv1.x;
    o1.y = a[5] * inv + xr1.y + bv1.y;
    o1.z = a[6] * inv + xr1.z + bv1.z;
    o1.w = a[7] * inv + xr1.w + bv1.w;
    if (do_relu) {
        o0.x = fmaxf(o0.x, 0.f); o0.y = fmaxf(o0.y, 0.f);
        o0.z = fmaxf(o0.z, 0.f); o0.w = fmaxf(o0.w, 0.f);
        o1.x = fmaxf(o1.x, 0.f); o1.y = fmaxf(o1.y, 0.f);
        o1.z = fmaxf(o1.z, 0.f); o1.w = fmaxf(o1.w, 0.f);
    }
    *(float4*)(out + (size_t)node * D + c * 8) = o0;
    *(float4*)(out + (size_t)node * D + c * 8 + 4) = o1;
}

// ---------------- launch (fork CSR build onto a side stream) ----------------
extern "C" void kernel_launch(void* const* d_in, const int* in_sizes, int n_in,
                              void* d_out, int out_size) {
    const float* x   = (const float*)d_in[0];
    const void*  ei  = d_in[1];
    const float* W1l = (const float*)d_in[2];
    const float* W1r = (const float*)d_in[3];
    const float* b1  = (const float*)d_in[4];
    const float* W2l = (const float*)d_in[5];
    const float* W2r = (const float*)d_in[6];
    const float* b2  = (const float*)d_in[7];
    float* out = (float*)d_out;

    static cudaStream_t s_side = nullptr;
    static cudaEvent_t ev_fork = nullptr, ev_join = nullptr;
    if (!s_side) {
        cudaStreamCreateWithFlags(&s_side, cudaStreamNonBlocking);
        cudaEventCreateWithFlags(&ev_fork, cudaEventDisableTiming);
        cudaEventCreateWithFlags(&ev_join, cudaEventDisableTiming);
    }

    const int E_BLOCKS   = (N_EDGES + 255) / 256;
    const int MM_BLOCKS  = (N_NODES + 127) / 128;
    const int AGG_BLOCKS = (N_NODES * 8 + 255) / 256;

    void* p_deg = nullptr;
    void* p_st  = nullptr;
    cudaGetSymbolAddress(&p_deg, g_deg);
    cudaGetSymbolAddress(&p_st, g_status);

    // fork: CSR build runs on side stream, concurrent with layer-1 projection
    cudaEventRecord(ev_fork, 0);
    cudaStreamWaitEvent(s_side, ev_fork, 0);
    cudaMemsetAsync(p_deg, 0, N_NODES * sizeof(int), s_side);
    cudaMemsetAsync(p_st, 0, SCAN_NBLK * sizeof(unsigned long long), s_side);
    hist_kernel<<<E_BLOCKS, 256, 0, s_side>>>(ei);
    scan_lookback_kernel<<<SCAN_NBLK, 256, 0, s_side>>>();
    scatter_kernel<<<E_BLOCKS, 256, 0, s_side>>>(ei);
    cudaEventRecord(ev_join, s_side);

    // layer-1 projection (HMMA tensor cores; independent of CSR)
    proj_mma_kernel<<<MM_BLOCKS, 256>>>(x, W1l, W1r);

    // join, then the serial chain
    cudaStreamWaitEvent(0, ev_join, 0);
    agg_combine_kernel<<<AGG_BLOCKS, 256>>>(b1, nullptr, 1);        // -> g_h (relu)
    proj_mma_kernel<<<MM_BLOCKS, 256>>>(nullptr, W2l, W2r);         // g_h proj
    agg_combine_kernel<<<AGG_BLOCKS, 256>>>(b2, out, 0);            // -> d_out
}